// round 6
// baseline (speedup 1.0000x reference)
#include <cuda_runtime.h>

#define CNUM 4
#define KNUM 128
#define DSUB 128
#define NTOK (64*2048)     /* 131072 tokens */
#define TT   128           /* tokens per block */
#define NTHREADS 256

#define XDUP_STRIDE 129    /* float2 row stride: 129 % 16 == 1 -> conflict-free */
#define XDUP_FLOATS (TT * XDUP_STRIDE * 2)   /* 33024 floats */

// scratch (allocation-free rule: __device__ globals)
__device__ float g_ET[CNUM*DSUB*KNUM];   // [c][j][k]  transposed embeddings
__device__ float g_e2[CNUM*KNUM];        // [c][k]     ||e||^2

// ---------------- pre-kernels ----------------
__global__ void vq_pre_transpose(const float* __restrict__ emb){
    int idx = blockIdx.x * blockDim.x + threadIdx.x;      // 65536 total
    int c = idx >> 14;
    int r = idx & 16383;
    int j = r >> 7;
    int k = r & 127;
    g_ET[idx] = emb[(c << 14) + (k << 7) + j];
}

// e2 mirrors the XLA-GPU row-reduction bit-for-bit (frozen: this passed).
__global__ void vq_pre_e2(const float* __restrict__ emb){
    int row  = blockIdx.x * 8 + (threadIdx.x >> 5);       // 512 rows, warp/row
    int lane = threadIdx.x & 31;
    if (row < CNUM * KNUM){
        float4 v = ((const float4*)(emb + row * DSUB))[lane];
        float t = __fmul_rn(v.x, v.x);
        t = __fmaf_rn(v.y, v.y, t);
        t = __fmaf_rn(v.z, v.z, t);
        t = __fmaf_rn(v.w, v.w, t);
        #pragma unroll
        for (int off = 16; off; off >>= 1)
            t = __fadd_rn(t, __shfl_xor_sync(0xffffffffu, t, off));
        if (lane == 0) g_e2[row] = t;
    }
}

// ---------------- main kernel ----------------
__global__ __launch_bounds__(NTHREADS) void vq_main(
    const float* __restrict__ xin,
    const float* __restrict__ emb,
    float* __restrict__ out)
{
    extern __shared__ float sm[];
    float2* xdp   = (float2*)sm;                 // [TT][129] duplicated x pairs
    float*  es    = sm + XDUP_FLOATS;            // [DSUB][KNUM] transposed E (64KB)
    float*  e2s   = es + DSUB*KNUM;              // 128
    float*  x2s   = e2s + 128;                   // 128
    float*  loss_s= x2s + 128;                   // 128
    int*    bestk_s = (int*)(loss_s + 128);      // 128
    int*    enc_s   = bestk_s + 128;             // 128

    const int tid  = threadIdx.x;
    const int lane = tid & 31;
    const int warp = tid >> 5;
    const int tx   = tid & 15;             // code group: pairs k0 = 2*tx + 32*p
    const int ty   = tid >> 4;             // token group (8 tokens)
    const int tok0 = blockIdx.x * TT;

    if (tid < TT){ loss_s[tid] = 0.f; enc_s[tid] = 0; }

    #pragma unroll 1
    for (int c = 0; c < CNUM; ++c){
        // ---- stage E^T tile + duplicated-x tile + e2 ----
        {
            const float4* esrc = (const float4*)(g_ET + (c << 14));
            float4* edst = (float4*)es;
            const float4* xsrc = (const float4*)xin;
            #pragma unroll
            for (int i = 0; i < 16; ++i){
                int f = tid + (i << 8);               // 0..4095
                edst[f] = esrc[f];
                int t = f >> 5, g4 = f & 31;          // token, float4-group
                float4 v = xsrc[(size_t)(tok0 + t) * 128 + (c << 5) + g4];
                float2* wp = xdp + t * XDUP_STRIDE + (g4 << 2);
                wp[0] = make_float2(v.x, v.x);
                wp[1] = make_float2(v.y, v.y);
                wp[2] = make_float2(v.z, v.z);
                wp[3] = make_float2(v.w, v.w);
            }
            if (tid < 128) e2s[tid] = g_e2[(c << 7) + tid];
        }
        __syncthreads();

        // ---- x2 per token: EXACT XLA row-reduce order (elements 4l..4l+3,
        //      mul+fma chain, warp xor tree) — reads .x of duplicated pairs ----
        #pragma unroll 1
        for (int i = 0; i < 16; ++i){
            int t = warp + (i << 3);
            const float2* rp = xdp + t * XDUP_STRIDE + (lane << 2);
            float a0 = rp[0].x, a1 = rp[1].x, a2 = rp[2].x, a3 = rp[3].x;
            float s = __fmul_rn(a0, a0);
            s = __fmaf_rn(a1, a1, s);
            s = __fmaf_rn(a2, a2, s);
            s = __fmaf_rn(a3, a3, s);
            #pragma unroll
            for (int off = 16; off; off >>= 1)
                s = __fadd_rn(s, __shfl_xor_sync(0xffffffffu, s, off));
            if (lane == 0) x2s[t] = s;
        }
        __syncthreads();

        // ---- dots: 8 tokens x 8 codes (4 interleaved pairs) per thread ----
        // Pure loop body: 4 LDS.64 (e pairs) + 8 LDS.64 (x dup) + 32 FFMA2.
        // Sequential j=0..127 fused chain per output: bit-matches cuBLAS.
        unsigned long long acc[8][4];
        #pragma unroll
        for (int m = 0; m < 8; ++m)
            #pragma unroll
            for (int p = 0; p < 4; ++p) acc[m][p] = 0ull;

        const unsigned long long* xrow =
            (const unsigned long long*)(xdp + (ty << 3) * XDUP_STRIDE);
        const unsigned long long* ebase =
            (const unsigned long long*)(es) + tx;   // float2 index tx (= 2*tx floats)

        #pragma unroll 2
        for (int j = 0; j < DSUB; ++j){
            const unsigned long long* ej = ebase + (j << 6);  // + j*64 float2
            unsigned long long e0 = ej[0], e1 = ej[16], e2v = ej[32], e3 = ej[48];
            #pragma unroll
            for (int m = 0; m < 8; ++m){
                unsigned long long xd = xrow[m * XDUP_STRIDE + j];
                asm("fma.rn.f32x2 %0, %1, %2, %0;" : "+l"(acc[m][0]) : "l"(xd), "l"(e0));
                asm("fma.rn.f32x2 %0, %1, %2, %0;" : "+l"(acc[m][1]) : "l"(xd), "l"(e1));
                asm("fma.rn.f32x2 %0, %1, %2, %0;" : "+l"(acc[m][2]) : "l"(xd), "l"(e2v));
                asm("fma.rn.f32x2 %0, %1, %2, %0;" : "+l"(acc[m][3]) : "l"(xd), "l"(e3));
            }
        }

        // ---- argmin over 128 codes (local 8 ascending-k, then 16-lane shuffle) ----
        const int powc = (c == 0) ? 2097152 : (c == 1) ? 16384 : (c == 2) ? 128 : 1;
        #pragma unroll
        for (int m = 0; m < 8; ++m){
            int t = (ty << 3) + m;
            float x2v = x2s[t];
            float best = 3.4e38f; int bk = 0;
            #pragma unroll
            for (int p = 0; p < 4; ++p){
                float lo, hi;
                asm("mov.b64 {%0, %1}, %2;" : "=f"(lo), "=f"(hi) : "l"(acc[m][p]));
                int k0 = (tx << 1) + (p << 5);      // 2*tx + 32*p (ascending in p)
                float s0 = __fadd_rn(__fadd_rn(x2v, e2s[k0]),     -2.0f * lo);
                float s1 = __fadd_rn(__fadd_rn(x2v, e2s[k0 + 1]), -2.0f * hi);
                if (s0 < best){ best = s0; bk = k0; }
                if (s1 < best){ best = s1; bk = k0 + 1; }
            }
            #pragma unroll
            for (int off = 1; off < 16; off <<= 1){
                float ob = __shfl_xor_sync(0xffffffffu, best, off);
                int   ok = __shfl_xor_sync(0xffffffffu, bk,   off);
                if (ob < best || (ob == best && ok < bk)){ best = ob; bk = ok; }
            }
            if (tx == 0){ bestk_s[t] = bk; enc_s[t] += bk * powc; }
        }
        __syncthreads();

        // ---- epilogue: write quantized + accumulate loss ----
        #pragma unroll 1
        for (int i = 0; i < 16; ++i){
            int t = warp + (i << 3);
            int kq = bestk_s[t];
            float4 e4 = ((const float4*)emb)[((c << 7) + kq) * 32 + lane];
            const float2* rp = xdp + t * XDUP_STRIDE + (lane << 2);
            float x0 = rp[0].x, x1 = rp[1].x, x2 = rp[2].x, x3 = rp[3].x;
            ((float4*)out)[(size_t)(tok0 + t) * 128 + (c << 5) + lane] = e4;
            float dx = e4.x - x0, dy = e4.y - x1, dz = e4.z - x2, dw = e4.w - x3;
            float d2 = dx*dx + dy*dy + dz*dz + dw*dw;
            #pragma unroll
            for (int off = 16; off; off >>= 1) d2 += __shfl_xor_sync(0xffffffffu, d2, off);
            if (lane == 0) loss_s[t] += d2;
        }
        __syncthreads();
    }

    // ---- final per-token scalars: encoding index (as fp32) and loss ----
    if (tid < TT){
        int gt = tok0 + tid;
        out[(size_t)NTOK * 512 + gt]        = (float)enc_s[tid];
        out[(size_t)NTOK * 512 + NTOK + gt] = 1.25f * loss_s[tid];
    }
}

// ---------------- launch ----------------
extern "C" void kernel_launch(void* const* d_in, const int* in_sizes, int n_in,
                              void* d_out, int out_size)
{
    const float* x   = (const float*)d_in[0];
    const float* emb = (const float*)d_in[1];
    float* out = (float*)d_out;

    const int smem_bytes = (XDUP_FLOATS + DSUB*KNUM + 128*3) * 4 + 128*2*4; // 200192 B
    cudaFuncSetAttribute(vq_main, cudaFuncAttributeMaxDynamicSharedMemorySize, smem_bytes);

    vq_pre_transpose<<<256, 256>>>(emb);
    vq_pre_e2<<<64, 256>>>(emb);
    vq_main<<<NTOK / TT, NTHREADS, smem_bytes>>>(x, emb, out);
}

// round 7
// speedup vs baseline: 2.1275x; 2.1275x over previous
#include <cuda_runtime.h>

#define CNUM 4
#define KNUM 128
#define DSUB 128
#define NTOK (64*2048)     /* 131072 tokens */
#define TT   128           /* tokens per block */
#define NTHREADS 256

// scratch (allocation-free rule: __device__ globals)
__device__ float g_ET[CNUM*DSUB*KNUM];   // [c][j][k]  transposed embeddings
__device__ float g_e2[CNUM*KNUM];        // [c][k]     ||e||^2

// ---------------- merged pre-kernel ----------------
// blocks 0..255: transpose E -> g_ET ; blocks 256..319: e2 rows (warp/row)
// e2 mirrors the XLA-GPU row-reduction bit-for-bit (frozen: passed at 5.7e-8).
__global__ void vq_pre(const float* __restrict__ emb){
    if (blockIdx.x < 256){
        int idx = blockIdx.x * 256 + threadIdx.x;         // 65536 total
        int c = idx >> 14;
        int r = idx & 16383;
        int j = r >> 7;
        int k = r & 127;
        g_ET[idx] = emb[(c << 14) + (k << 7) + j];
    } else {
        int row  = (blockIdx.x - 256) * 8 + (threadIdx.x >> 5);   // 512 rows
        int lane = threadIdx.x & 31;
        if (row < CNUM * KNUM){
            float4 v = ((const float4*)(emb + row * DSUB))[lane];
            float t = __fmul_rn(v.x, v.x);
            t = __fmaf_rn(v.y, v.y, t);
            t = __fmaf_rn(v.z, v.z, t);
            t = __fmaf_rn(v.w, v.w, t);
            #pragma unroll
            for (int off = 16; off; off >>= 1)
                t = __fadd_rn(t, __shfl_xor_sync(0xffffffffu, t, off));
            if (lane == 0) g_e2[row] = t;
        }
    }
}

// ---------------- main kernel ----------------
__global__ __launch_bounds__(NTHREADS) void vq_main(
    const float* __restrict__ xin,
    const float* __restrict__ emb,
    float* __restrict__ out)
{
    extern __shared__ float sm[];
    float* xs     = sm;                    // [TT][DSUB]     16384 f
    float* es     = sm + 16384;            // [DSUB][KNUM]   16384 f (transposed E)
    float* e2s    = sm + 32768;            // 128
    float* x2s    = e2s + 128;             // 128
    float* loss_s = x2s + 128;             // 128
    int*   bestk_s = (int*)(loss_s + 128); // 128
    int*   enc_s   = bestk_s + 128;        // 128

    const int tid  = threadIdx.x;
    const int lane = tid & 31;
    const int warp = tid >> 5;
    const int tx   = tid & 15;             // code group: pairs k0 = 2*tx + 32*p
    const int ty   = tid >> 4;             // token group (8 tokens)
    const int tok0 = blockIdx.x * TT;

    if (tid < TT){ loss_s[tid] = 0.f; enc_s[tid] = 0; }

    #pragma unroll 1
    for (int c = 0; c < CNUM; ++c){
        // ---- stage E^T tile + x tile + e2 ----
        {
            const float4* esrc = (const float4*)(g_ET + (c << 14));
            float4* edst = (float4*)es;
            const float4* xsrc = (const float4*)xin;
            float4* xdst = (float4*)xs;
            #pragma unroll
            for (int i = 0; i < 16; ++i){
                int f = tid + (i << 8);
                edst[f] = esrc[f];
                int t = f >> 5, j4 = f & 31;
                xdst[f] = xsrc[(size_t)(tok0 + t) * 128 + (c << 5) + j4];
            }
            if (tid < 128) e2s[tid] = g_e2[(c << 7) + tid];
        }
        __syncthreads();

        // ---- x2 per token: EXACT XLA row-reduce order (float4/lane,
        //      mul+fma chain, warp xor tree) — frozen numerics ----
        #pragma unroll 1
        for (int i = 0; i < 16; ++i){
            int t = warp + (i << 3);
            float4 v = ((const float4*)xs)[(t << 5) + lane];
            float s = __fmul_rn(v.x, v.x);
            s = __fmaf_rn(v.y, v.y, s);
            s = __fmaf_rn(v.z, v.z, s);
            s = __fmaf_rn(v.w, v.w, s);
            #pragma unroll
            for (int off = 16; off; off >>= 1)
                s = __fadd_rn(s, __shfl_xor_sync(0xffffffffu, s, off));
            if (lane == 0) x2s[t] = s;
        }
        __syncthreads();

        // ---- dots: 8 tokens x 8 codes (4 interleaved pairs) per thread ----
        // e pairs at float2 index tx + 16p (+64j): bank = tx -> conflict-free.
        // x scalar loads broadcast across the 16 lanes sharing ty.
        // Sequential j=0..127 fused chain per output: bit-matches reference.
        unsigned long long acc[8][4];
        #pragma unroll
        for (int m = 0; m < 8; ++m)
            #pragma unroll
            for (int p = 0; p < 4; ++p) acc[m][p] = 0ull;

        const float* xp = xs + (ty << 3) * DSUB;
        const unsigned long long* ebase =
            (const unsigned long long*)(es) + tx;     // float2 index tx

        #pragma unroll 4
        for (int j = 0; j < DSUB; ++j){
            const unsigned long long* ej = ebase + (j << 6);   // +64 float2 per j
            unsigned long long e0 = ej[0], e1 = ej[16], e2v = ej[32], e3 = ej[48];
            #pragma unroll
            for (int m = 0; m < 8; ++m){
                float xv = xp[m * DSUB + j];
                unsigned long long xd;
                asm("mov.b64 %0, {%1, %1};" : "=l"(xd) : "f"(xv));
                asm("fma.rn.f32x2 %0, %1, %2, %0;" : "+l"(acc[m][0]) : "l"(xd), "l"(e0));
                asm("fma.rn.f32x2 %0, %1, %2, %0;" : "+l"(acc[m][1]) : "l"(xd), "l"(e1));
                asm("fma.rn.f32x2 %0, %1, %2, %0;" : "+l"(acc[m][2]) : "l"(xd), "l"(e2v));
                asm("fma.rn.f32x2 %0, %1, %2, %0;" : "+l"(acc[m][3]) : "l"(xd), "l"(e3));
            }
        }

        // ---- argmin over 128 codes (local 8 ascending-k, then 16-lane shuffle) ----
        const int powc = (c == 0) ? 2097152 : (c == 1) ? 16384 : (c == 2) ? 128 : 1;
        #pragma unroll
        for (int m = 0; m < 8; ++m){
            int t = (ty << 3) + m;
            float x2v = x2s[t];
            float best = 3.4e38f; int bk = 0;
            #pragma unroll
            for (int p = 0; p < 4; ++p){
                float lo, hi;
                asm("mov.b64 {%0, %1}, %2;" : "=f"(lo), "=f"(hi) : "l"(acc[m][p]));
                int k0 = (tx << 1) + (p << 5);        // 2*tx + 32*p (ascending in p)
                float s0 = __fadd_rn(__fadd_rn(x2v, e2s[k0]),     -2.0f * lo);
                float s1 = __fadd_rn(__fadd_rn(x2v, e2s[k0 + 1]), -2.0f * hi);
                if (s0 < best){ best = s0; bk = k0; }
                if (s1 < best){ best = s1; bk = k0 + 1; }
            }
            #pragma unroll
            for (int off = 1; off < 16; off <<= 1){
                float ob = __shfl_xor_sync(0xffffffffu, best, off);
                int   ok = __shfl_xor_sync(0xffffffffu, bk,   off);
                if (ob < best || (ob == best && ok < bk)){ best = ob; bk = ok; }
            }
            if (tx == 0){ bestk_s[t] = bk; enc_s[t] += bk * powc; }
        }
        __syncthreads();

        // ---- epilogue: write quantized + accumulate loss ----
        #pragma unroll 1
        for (int i = 0; i < 16; ++i){
            int t = warp + (i << 3);
            int kq = bestk_s[t];
            float4 e4 = ((const float4*)emb)[((c << 7) + kq) * 32 + lane];
            float4 x4 = ((const float4*)xs)[(t << 5) + lane];
            ((float4*)out)[(size_t)(tok0 + t) * 128 + (c << 5) + lane] = e4;
            float dx = e4.x - x4.x, dy = e4.y - x4.y, dz = e4.z - x4.z, dw = e4.w - x4.w;
            float d2 = dx*dx + dy*dy + dz*dz + dw*dw;
            #pragma unroll
            for (int off = 16; off; off >>= 1) d2 += __shfl_xor_sync(0xffffffffu, d2, off);
            if (lane == 0) loss_s[t] += d2;
        }
        __syncthreads();
    }

    // ---- final per-token scalars: encoding index (as fp32) and loss ----
    if (tid < TT){
        int gt = tok0 + tid;
        out[(size_t)NTOK * 512 + gt]        = (float)enc_s[tid];
        out[(size_t)NTOK * 512 + NTOK + gt] = 1.25f * loss_s[tid];
    }
}

// ---------------- launch ----------------
extern "C" void kernel_launch(void* const* d_in, const int* in_sizes, int n_in,
                              void* d_out, int out_size)
{
    const float* x   = (const float*)d_in[0];
    const float* emb = (const float*)d_in[1];
    float* out = (float*)d_out;

    const int smem_bytes = (16384 + 16384 + 128*3) * 4 + 128*2*4;  // 133632 B
    cudaFuncSetAttribute(vq_main, cudaFuncAttributeMaxDynamicSharedMemorySize, smem_bytes);

    vq_pre<<<320, 256>>>(emb);
    vq_main<<<NTOK / TT, NTHREADS, smem_bytes>>>(x, emb, out);
}

// round 8
// speedup vs baseline: 2.1771x; 1.0233x over previous
#include <cuda_runtime.h>

#define CNUM 4
#define KNUM 128
#define DSUB 128
#define NTOK (64*2048)     /* 131072 tokens */
#define TT   256           /* tokens per block */
#define NTHREADS 512

// scratch (allocation-free rule: __device__ globals)
__device__ float g_ET[CNUM*DSUB*KNUM];   // [c][j][k]  transposed embeddings
__device__ float g_e2[CNUM*KNUM];        // [c][k]     ||e||^2

// ---------------- merged pre-kernel ----------------
// blocks 0..255: transpose E -> g_ET ; blocks 256..319: e2 rows (warp/row)
// e2 mirrors the XLA-GPU row-reduction bit-for-bit (frozen: passed at 5.7e-8).
__global__ void vq_pre(const float* __restrict__ emb){
    if (blockIdx.x < 256){
        int idx = blockIdx.x * 256 + threadIdx.x;         // 65536 total
        int c = idx >> 14;
        int r = idx & 16383;
        int j = r >> 7;
        int k = r & 127;
        g_ET[idx] = emb[(c << 14) + (k << 7) + j];
    } else {
        int row  = (blockIdx.x - 256) * 8 + (threadIdx.x >> 5);   // 512 rows
        int lane = threadIdx.x & 31;
        if (row < CNUM * KNUM){
            float4 v = ((const float4*)(emb + row * DSUB))[lane];
            float t = __fmul_rn(v.x, v.x);
            t = __fmaf_rn(v.y, v.y, t);
            t = __fmaf_rn(v.z, v.z, t);
            t = __fmaf_rn(v.w, v.w, t);
            #pragma unroll
            for (int off = 16; off; off >>= 1)
                t = __fadd_rn(t, __shfl_xor_sync(0xffffffffu, t, off));
            if (lane == 0) g_e2[row] = t;
        }
    }
}

// ---------------- main kernel ----------------
__global__ __launch_bounds__(NTHREADS, 1) void vq_main(
    const float* __restrict__ xin,
    const float* __restrict__ emb,
    float* __restrict__ out)
{
    extern __shared__ float sm[];
    float* xs     = sm;                    // [TT][DSUB]     32768 f
    float* es     = sm + TT*DSUB;          // [DSUB][KNUM]   16384 f (transposed E)
    float* e2s    = es + DSUB*KNUM;        // 128
    float* x2s    = e2s + 128;             // 256
    float* loss_s = x2s + TT;              // 256
    int*   bestk_s = (int*)(loss_s + TT);  // 256
    int*   enc_s   = bestk_s + TT;         // 256

    const int tid  = threadIdx.x;
    const int lane = tid & 31;
    const int warp = tid >> 5;             // 0..15
    const int tx   = tid & 15;             // code group: pairs k0 = 2*tx + 32*p
    const int ty   = tid >> 4;             // token group (8 tokens), 0..31
    const int tok0 = blockIdx.x * TT;

    if (tid < TT){ loss_s[tid] = 0.f; enc_s[tid] = 0; }

    #pragma unroll 1
    for (int c = 0; c < CNUM; ++c){
        // ---- stage E^T tile + x tile + e2 ----
        {
            const float4* esrc = (const float4*)(g_ET + (c << 14));
            float4* edst = (float4*)es;
            const float4* xsrc = (const float4*)xin;
            float4* xdst = (float4*)xs;
            #pragma unroll
            for (int i = 0; i < 8; ++i){                 // es: 4096 float4
                int f = tid + (i << 9);
                edst[f] = esrc[f];
            }
            #pragma unroll
            for (int i = 0; i < 16; ++i){                // xs: 8192 float4
                int f = tid + (i << 9);
                int t = f >> 5, j4 = f & 31;
                xdst[f] = xsrc[(size_t)(tok0 + t) * 128 + (c << 5) + j4];
            }
            if (tid < 128) e2s[tid] = g_e2[(c << 7) + tid];
        }
        __syncthreads();

        // ---- x2 per token: EXACT XLA row-reduce order (float4/lane,
        //      mul+fma chain, warp xor tree) — frozen numerics ----
        #pragma unroll 1
        for (int i = 0; i < 16; ++i){
            int t = (i << 4) + warp;
            float4 v = ((const float4*)xs)[(t << 5) + lane];
            float s = __fmul_rn(v.x, v.x);
            s = __fmaf_rn(v.y, v.y, s);
            s = __fmaf_rn(v.z, v.z, s);
            s = __fmaf_rn(v.w, v.w, s);
            #pragma unroll
            for (int off = 16; off; off >>= 1)
                s = __fadd_rn(s, __shfl_xor_sync(0xffffffffu, s, off));
            if (lane == 0) x2s[t] = s;
        }
        __syncthreads();

        // ---- dots: 8 tokens x 8 codes (4 interleaved pairs) per thread ----
        // e pairs at float2 index tx + 16p (+64j): bank = tx -> conflict-free.
        // x scalar loads broadcast across the 16 lanes sharing ty.
        // Sequential j=0..127 fused chain per output: bit-matches reference.
        unsigned long long acc[8][4];
        #pragma unroll
        for (int m = 0; m < 8; ++m)
            #pragma unroll
            for (int p = 0; p < 4; ++p) acc[m][p] = 0ull;

        const float* xp = xs + (ty << 3) * DSUB;
        const unsigned long long* ebase =
            (const unsigned long long*)(es) + tx;     // float2 index tx

        #pragma unroll 2
        for (int j = 0; j < DSUB; ++j){
            const unsigned long long* ej = ebase + (j << 6);   // +64 float2 per j
            unsigned long long e0 = ej[0], e1 = ej[16], e2v = ej[32], e3 = ej[48];
            #pragma unroll
            for (int m = 0; m < 8; ++m){
                float xv = xp[m * DSUB + j];
                unsigned long long xd;
                asm("mov.b64 %0, {%1, %1};" : "=l"(xd) : "f"(xv));
                asm("fma.rn.f32x2 %0, %1, %2, %0;" : "+l"(acc[m][0]) : "l"(xd), "l"(e0));
                asm("fma.rn.f32x2 %0, %1, %2, %0;" : "+l"(acc[m][1]) : "l"(xd), "l"(e1));
                asm("fma.rn.f32x2 %0, %1, %2, %0;" : "+l"(acc[m][2]) : "l"(xd), "l"(e2v));
                asm("fma.rn.f32x2 %0, %1, %2, %0;" : "+l"(acc[m][3]) : "l"(xd), "l"(e3));
            }
        }

        // ---- argmin over 128 codes (local 8 ascending-k, then 16-lane shuffle) ----
        const int powc = (c == 0) ? 2097152 : (c == 1) ? 16384 : (c == 2) ? 128 : 1;
        #pragma unroll
        for (int m = 0; m < 8; ++m){
            int t = (ty << 3) + m;
            float x2v = x2s[t];
            float best = 3.4e38f; int bk = 0;
            #pragma unroll
            for (int p = 0; p < 4; ++p){
                float lo, hi;
                asm("mov.b64 {%0, %1}, %2;" : "=f"(lo), "=f"(hi) : "l"(acc[m][p]));
                int k0 = (tx << 1) + (p << 5);        // 2*tx + 32*p (ascending in p)
                float s0 = __fadd_rn(__fadd_rn(x2v, e2s[k0]),     -2.0f * lo);
                float s1 = __fadd_rn(__fadd_rn(x2v, e2s[k0 + 1]), -2.0f * hi);
                if (s0 < best){ best = s0; bk = k0; }
                if (s1 < best){ best = s1; bk = k0 + 1; }
            }
            #pragma unroll
            for (int off = 1; off < 16; off <<= 1){
                float ob = __shfl_xor_sync(0xffffffffu, best, off);
                int   ok = __shfl_xor_sync(0xffffffffu, bk,   off);
                if (ob < best || (ob == best && ok < bk)){ best = ob; bk = ok; }
            }
            if (tx == 0){ bestk_s[t] = bk; enc_s[t] += bk * powc; }
        }
        __syncthreads();

        // ---- epilogue: write quantized + accumulate loss ----
        #pragma unroll 1
        for (int i = 0; i < 16; ++i){
            int t = (i << 4) + warp;
            int kq = bestk_s[t];
            float4 e4 = ((const float4*)emb)[((c << 7) + kq) * 32 + lane];
            float4 x4 = ((const float4*)xs)[(t << 5) + lane];
            ((float4*)out)[(size_t)(tok0 + t) * 128 + (c << 5) + lane] = e4;
            float dx = e4.x - x4.x, dy = e4.y - x4.y, dz = e4.z - x4.z, dw = e4.w - x4.w;
            float d2 = dx*dx + dy*dy + dz*dz + dw*dw;
            #pragma unroll
            for (int off = 16; off; off >>= 1) d2 += __shfl_xor_sync(0xffffffffu, d2, off);
            if (lane == 0) loss_s[t] += d2;
        }
        __syncthreads();
    }

    // ---- final per-token scalars: encoding index (as fp32) and loss ----
    if (tid < TT){
        int gt = tok0 + tid;
        out[(size_t)NTOK * 512 + gt]        = (float)enc_s[tid];
        out[(size_t)NTOK * 512 + NTOK + gt] = 1.25f * loss_s[tid];
    }
}

// ---------------- launch ----------------
extern "C" void kernel_launch(void* const* d_in, const int* in_sizes, int n_in,
                              void* d_out, int out_size)
{
    const float* x   = (const float*)d_in[0];
    const float* emb = (const float*)d_in[1];
    float* out = (float*)d_out;

    const int smem_bytes = (TT*DSUB + DSUB*KNUM + 128 + TT*2) * 4 + TT*2*4; // ~200 KB
    cudaFuncSetAttribute(vq_main, cudaFuncAttributeMaxDynamicSharedMemorySize, smem_bytes);

    vq_pre<<<320, 256>>>(emb);
    vq_main<<<NTOK / TT, NTHREADS, smem_bytes>>>(x, emb, out);
}